// round 2
// baseline (speedup 1.0000x reference)
#include <cuda_runtime.h>
#include <math.h>

#define EPS 1e-8f
#define NB 64
#define NO 64
#define NI 1152
#define ND 16
#define INVT1 5.0e-4f            /* 0.01*(1-0.95)   */
#define INVT2 9.75e-4f           /* 0.01*(1-0.9025) */

/* ---------------- scratch (device globals: allocation-free) ---------------- */
__device__ float g_V[(long)NB * NI * NO * ND];   /* layout [b][i][o][e], 302 MB */
__device__ float g_ai[NB * NI];
__device__ float g_asum[NB];
__device__ float g_mean0[NB * NO * ND];
__device__ float g_inv2[NB * NO * ND];
__device__ float g_c[NB * NO];                   /* a_j0/(p1+EPS) */
__device__ float g_S[NB * NO * 33];              /* [0:16) wV, [16:32) wV^2, [32] w */

/* ---------------- K0: a_i = ||u+eps||, asum[b] = sum_i a_i ---------------- */
__global__ void k0_ai(const float* __restrict__ u) {
    int b = blockIdx.x, tid = threadIdx.x;
    float part = 0.f;
    for (int i = tid; i < NI; i += 256) {
        const float* ur = u + (b * NI + i) * ND;
        float s = 0.f;
#pragma unroll
        for (int d = 0; d < ND; d++) { float x = ur[d] + EPS; s += x * x; }
        float a = sqrtf(s);
        g_ai[b * NI + i] = a;
        part += a;
    }
    __shared__ float sm[256];
    sm[tid] = part; __syncthreads();
    for (int s = 128; s > 0; s >>= 1) { if (tid < s) sm[tid] += sm[tid + s]; __syncthreads(); }
    if (tid == 0) g_asum[b] = sm[0];
}

/* ---------------- K1: votes V + m-step-1 (uniform rr) ----------------
 * grid (o, btile of 8 b's); threads 256 = (i16, e). W rows held in regs,
 * u chunk staged in smem. Writes V[b][i][o][e]; accumulates a_i*V, a_i*V^2.
 */
__global__ __launch_bounds__(256) void k1_votes(
    const float4* __restrict__ u4, const float4* __restrict__ W4,
    const float* __restrict__ beta_a, const float* __restrict__ beta_u,
    const float* __restrict__ bias)
{
    int o = blockIdx.x, b0 = blockIdx.y * 8;
    int tid = threadIdx.x, e = tid & 15, i16 = tid >> 4;

    __shared__ float4 us[8][16][4];    /* [b][i][d4] */
    __shared__ float  ai_s[8][16];
    __shared__ float  redS[16][8][16]; /* [i16][b][e] */
    __shared__ float  redQ[16][8][16];

    float accS[8], accQ[8];
#pragma unroll
    for (int b = 0; b < 8; b++) { accS[b] = 0.f; accQ[b] = 0.f; }
    float biasv = EPS + bias[o * ND + e];

    for (int c = 0; c < NI / 16; c++) {
        int ibase = c * 16;
        /* stage u chunk: 8b x 16i x 4 float4 = 512 */
        for (int idx = tid; idx < 512; idx += 256) {
            int b = idx >> 6, rem = idx & 63, ii = rem >> 2, d4 = rem & 3;
            us[b][ii][d4] = u4[((b0 + b) * NI + ibase + ii) * 4 + d4];
        }
        if (tid < 128) {
            int b = tid >> 4, ii = tid & 15;
            ai_s[b][ii] = g_ai[(b0 + b) * NI + ibase + ii];
        }
        __syncthreads();

        int i = ibase + i16;
        const float4* wr = W4 + ((size_t)(o * NI + i) * ND + e) * 4;
        float4 w0 = wr[0], w1 = wr[1], w2 = wr[2], w3 = wr[3];
#pragma unroll
        for (int b = 0; b < 8; b++) {
            float4 a0 = us[b][i16][0], a1 = us[b][i16][1];
            float4 a2 = us[b][i16][2], a3 = us[b][i16][3];
            float v = biasv;
            v = fmaf(a0.x, w0.x, v); v = fmaf(a0.y, w0.y, v);
            v = fmaf(a0.z, w0.z, v); v = fmaf(a0.w, w0.w, v);
            v = fmaf(a1.x, w1.x, v); v = fmaf(a1.y, w1.y, v);
            v = fmaf(a1.z, w1.z, v); v = fmaf(a1.w, w1.w, v);
            v = fmaf(a2.x, w2.x, v); v = fmaf(a2.y, w2.y, v);
            v = fmaf(a2.z, w2.z, v); v = fmaf(a2.w, w2.w, v);
            v = fmaf(a3.x, w3.x, v); v = fmaf(a3.y, w3.y, v);
            v = fmaf(a3.z, w3.z, v); v = fmaf(a3.w, w3.w, v);
            g_V[((b0 + b) * NI + i) * (NO * ND) + o * ND + e] = v;
            float a = ai_s[b][i16];
            float t = a * v;
            accS[b] += t;
            accQ[b] = fmaf(t, v, accQ[b]);
        }
        __syncthreads();
    }

#pragma unroll
    for (int b = 0; b < 8; b++) { redS[i16][b][e] = accS[b]; redQ[i16][b][e] = accQ[b]; }
    __syncthreads();

    if (tid < 128) {
        int b = tid >> 4, ee = tid & 15;
        float S = 0.f, Q = 0.f;
#pragma unroll
        for (int k = 0; k < 16; k++) { S += redS[k][b][ee]; Q += redQ[k][b][ee]; }
        S *= (1.0f / NO); Q *= (1.0f / NO);         /* rr = 1/O uniform */
        float rs  = g_asum[b0 + b] * (1.0f / NO);   /* rr_sum */
        float inv = 1.0f / (rs + EPS);
        float m   = S * inv;
        float var = (Q - 2.0f * m * S + m * m * rs) * inv + 1e-4f;
        float lv  = logf(var);
        float lsum = lv;
#pragma unroll
        for (int off = 8; off; off >>= 1) lsum += __shfl_xor_sync(0xffffffffu, lsum, off);
        float bu   = beta_u[o];
        float cost = rs * (16.0f * bu + lsum);
        float aj   = 1.0f / (1.0f + expf(-INVT1 * (beta_a[o] - cost)));
        float p1   = sqrtf(2.0f * 3.14159265358979323846f * expf(lsum) + EPS);
        int bo = (b0 + b) * NO + o;
        g_mean0[bo * ND + ee] = m;
        g_inv2[bo * ND + ee]  = 1.0f / (2.0f * var + EPS);
        if (ee == 0) g_c[bo] = aj / (p1 + EPS);
        /* zero accumulators for K2 (runs before K2 in-stream) */
        g_S[bo * 33 + ee] = 0.f;
        g_S[bo * 33 + 16 + ee] = 0.f;
        if (ee == 0) g_S[bo * 33 + 32] = 0.f;
    }
}

/* ---------------- K2: fused e-step + m-step-2 accumulation ----------------
 * grid (b, 4 i-chunks of 288); threads 256 = (isub 0..3) x (o 0..63).
 * One coalesced pass over V; per-i cross-o denom via shuffle + smem;
 * per-thread accumulators (o fixed per thread) -> atomicAdd at end.
 */
__global__ __launch_bounds__(256, 2) void k2_route(void)
{
    int b = blockIdx.x, istart = blockIdx.y * 288;
    int tid = threadIdx.x, o = tid & 63, isub = tid >> 6;
    int bo = b * NO + o;

    float m[16], iv[16];
#pragma unroll
    for (int e = 0; e < 16; e++) { m[e] = g_mean0[bo * ND + e]; iv[e] = g_inv2[bo * ND + e]; }
    float cc = g_c[bo];

    float accw = 0.f, accv[16], accq[16];
#pragma unroll
    for (int e = 0; e < 16; e++) { accv[e] = 0.f; accq[e] = 0.f; }

    __shared__ float wsum[8];
    const float4* V4 = (const float4*)g_V;

    int i0 = istart + isub;
    const float4* p = V4 + ((size_t)(b * NI + i0) * NO + o) * 4;
    float4 r0 = p[0], r1 = p[1], r2 = p[2], r3 = p[3];

    for (int j = 0; j < 72; j++) {
        float4 c0 = r0, c1 = r1, c2 = r2, c3 = r3;
        if (j < 71) {
            const float4* q = V4 + ((size_t)(b * NI + i0 + 4 * (j + 1)) * NO + o) * 4;
            r0 = q[0]; r1 = q[1]; r2 = q[2]; r3 = q[3];
        }
        int i = i0 + 4 * j;
        float V[16];
        V[0]=c0.x; V[1]=c0.y; V[2]=c0.z; V[3]=c0.w;
        V[4]=c1.x; V[5]=c1.y; V[6]=c1.z; V[7]=c1.w;
        V[8]=c2.x; V[9]=c2.y; V[10]=c2.z; V[11]=c2.w;
        V[12]=c3.x; V[13]=c3.y; V[14]=c3.z; V[15]=c3.w;

        float la = 0.f;
#pragma unroll
        for (int e = 0; e < 16; e++) { float d = V[e] - m[e]; la = fmaf(d * d, iv[e], la); }
        float ap = cc * __expf(-la);

        float s = ap;
#pragma unroll
        for (int off = 16; off; off >>= 1) s += __shfl_xor_sync(0xffffffffu, s, off);
        if ((tid & 31) == 0) wsum[tid >> 5] = s;
        __syncthreads();
        float denom = wsum[isub * 2] + wsum[isub * 2 + 1];
        __syncthreads();

        float ai = __ldg(&g_ai[b * NI + i]);
        float wt = ap * ai / (denom + EPS);
        accw += wt;
#pragma unroll
        for (int e = 0; e < 16; e++) {
            accv[e] = fmaf(wt, V[e], accv[e]);
            accq[e] = fmaf(wt * V[e], V[e], accq[e]);
        }
    }

    float* dst = g_S + bo * 33;
#pragma unroll
    for (int e = 0; e < 16; e++) {
        atomicAdd(dst + e, accv[e]);
        atomicAdd(dst + 16 + e, accq[e]);
    }
    atomicAdd(dst + 32, accw);
}

/* ---------------- K3: finalize m-step-2 + output ---------------- */
__global__ void k3_final(const float* __restrict__ beta_a,
                         const float* __restrict__ beta_u,
                         float* __restrict__ out)
{
    int bo = blockIdx.x * 256 + threadIdx.x;
    if (bo >= NB * NO) return;
    int o = bo & 63;
    const float* s = g_S + bo * 33;
    float rs  = s[32];
    float inv = 1.0f / (rs + EPS);
    float bu  = beta_u[o];
    float mm[16];
    float cost = 0.f, norm2 = 0.f;
#pragma unroll
    for (int e = 0; e < 16; e++) {
        float sv = s[e], sq = s[16 + e];
        float me = sv * inv;
        float var = (sq - 2.0f * me * sv + me * me * rs) * inv + 1e-4f;
        cost += bu + logf(var);
        mm[e] = me;
        float t = me + EPS;
        norm2 = fmaf(t, t, norm2);
    }
    cost *= rs;
    float aj = 1.0f / (1.0f + expf(-INVT2 * (beta_a[o] - cost)));
    float scale = aj / (sqrtf(norm2) + EPS);
#pragma unroll
    for (int e = 0; e < 16; e++) out[bo * ND + e] = mm[e] * scale;
}

/* ---------------- launch ---------------- */
extern "C" void kernel_launch(void* const* d_in, const int* in_sizes, int n_in,
                              void* d_out, int out_size)
{
    const float* u      = (const float*)d_in[0];
    const float* W      = (const float*)d_in[1];
    const float* beta_a = (const float*)d_in[2];
    const float* beta_u = (const float*)d_in[3];
    const float* bias   = (const float*)d_in[4];
    float* out = (float*)d_out;

    k0_ai<<<NB, 256>>>(u);
    k1_votes<<<dim3(NO, 8), 256>>>((const float4*)u, (const float4*)W,
                                   beta_a, beta_u, bias);
    k2_route<<<dim3(NB, 4), 256>>>();
    k3_final<<<16, 256>>>(beta_a, beta_u, out);
}

// round 4
// speedup vs baseline: 1.1668x; 1.1668x over previous
#include <cuda_runtime.h>
#include <math.h>

#define EPS 1e-8f
#define NB 64
#define NO 64
#define NI 1152
#define ND 16
#define INVT1 5.0e-4f            /* 0.01*(1-0.95)   */
#define INVT2 9.75e-4f           /* 0.01*(1-0.9025) */

/* ---------------- scratch (device globals: allocation-free) ---------------- */
__device__ float g_V[(size_t)NB * NI * NO * ND];   /* layout [b][i][o][e], 302 MB */
__device__ float g_ai[NB * NI];
__device__ float g_asum[NB];
__device__ float g_S1S[NB * NO * ND];              /* stage-1: sum a_i*V   */
__device__ float g_S1Q[NB * NO * ND];              /* stage-1: sum a_i*V^2 */
__device__ float g_mean0[NB * NO * ND];
__device__ float g_inv2[NB * NO * ND];
__device__ float g_c[NB * NO];                     /* a_j0/(p1+EPS) */
__device__ float g_S[NB * NO * 33];                /* [0:16) wV, [16:32) wV^2, [32] w */

/* ---------------- K0: a_i = ||u+eps||, asum[b]; zero stage-1 accumulators -- */
__global__ void k0_ai(const float* __restrict__ u) {
    int b = blockIdx.x, tid = threadIdx.x;
    /* zero g_S1S/g_S1Q slices for this b (1024 floats each) */
    for (int k = tid; k < 1024; k += 256) {
        g_S1S[b * 1024 + k] = 0.f;
        g_S1Q[b * 1024 + k] = 0.f;
    }
    float part = 0.f;
    for (int i = tid; i < NI; i += 256) {
        const float* ur = u + (b * NI + i) * ND;
        float s = 0.f;
#pragma unroll
        for (int d = 0; d < ND; d++) { float x = ur[d] + EPS; s += x * x; }
        float a = sqrtf(s);
        g_ai[b * NI + i] = a;
        part += a;
    }
    __shared__ float sm[256];
    sm[tid] = part; __syncthreads();
    for (int s = 128; s > 0; s >>= 1) { if (tid < s) sm[tid] += sm[tid + s]; __syncthreads(); }
    if (tid == 0) g_asum[b] = sm[0];
}

/* ---------------- K1: votes V + stage-1 partial sums ----------------
 * grid (o=64, ichunk=18): block owns i-range of 64, loops ALL 64 b's.
 * W read EXACTLY ONCE from DRAM (held in 64 regs/thread).
 * threads 256 = (i16=16) x (e=16), e minor (coalesced V stores).
 */
__global__ __launch_bounds__(256, 2) void k1_votes(
    const float4* __restrict__ u4, const float4* __restrict__ W4,
    const float* __restrict__ bias)
{
    int o = blockIdx.x, i0 = blockIdx.y * 64;
    int tid = threadIdx.x, e = tid & 15, i16 = tid >> 4;

    __shared__ float4 us[8][64][4];    /* u for current b-group: 32 KB */
    __shared__ float  ai_s[8][64];     /* a_i for current b-group */
    __shared__ float  redS[16][8][16]; /* [i16][b][e] */
    __shared__ float  redQ[16][8][16];

    /* W rows for this thread's 4 i-tiles: 64 regs */
    float4 w[4][4];
#pragma unroll
    for (int it = 0; it < 4; it++) {
        const float4* wr = W4 + ((size_t)(o * NI + i0 + it * 16 + i16) * ND + e) * 4;
        w[it][0] = wr[0]; w[it][1] = wr[1]; w[it][2] = wr[2]; w[it][3] = wr[3];
    }
    float biasv = EPS + bias[o * ND + e];

    for (int g = 0; g < 8; g++) {
        int bbase = g * 8;
        __syncthreads();    /* prev group fully done (incl. red reads) */
        for (int idx = tid; idx < 2048; idx += 256) {
            int bs = idx >> 8, rem = idx & 255, ii = rem >> 2, d4 = rem & 3;
            us[bs][ii][d4] = u4[((size_t)(bbase + bs) * NI + i0 + ii) * 4 + d4];
        }
        for (int idx = tid; idx < 512; idx += 256) {
            int bs = idx >> 6, ii = idx & 63;
            ai_s[bs][ii] = g_ai[(bbase + bs) * NI + i0 + ii];
        }
        __syncthreads();

        float accS[8], accQ[8];
#pragma unroll
        for (int bs = 0; bs < 8; bs++) { accS[bs] = 0.f; accQ[bs] = 0.f; }

#pragma unroll
        for (int it = 0; it < 4; it++) {
            int ii = it * 16 + i16;
            int i  = i0 + ii;
#pragma unroll
            for (int bs = 0; bs < 8; bs++) {
                float4 a0 = us[bs][ii][0], a1 = us[bs][ii][1];
                float4 a2 = us[bs][ii][2], a3 = us[bs][ii][3];
                float v = biasv;
                v = fmaf(a0.x, w[it][0].x, v); v = fmaf(a0.y, w[it][0].y, v);
                v = fmaf(a0.z, w[it][0].z, v); v = fmaf(a0.w, w[it][0].w, v);
                v = fmaf(a1.x, w[it][1].x, v); v = fmaf(a1.y, w[it][1].y, v);
                v = fmaf(a1.z, w[it][1].z, v); v = fmaf(a1.w, w[it][1].w, v);
                v = fmaf(a2.x, w[it][2].x, v); v = fmaf(a2.y, w[it][2].y, v);
                v = fmaf(a2.z, w[it][2].z, v); v = fmaf(a2.w, w[it][2].w, v);
                v = fmaf(a3.x, w[it][3].x, v); v = fmaf(a3.y, w[it][3].y, v);
                v = fmaf(a3.w, w[it][3].w, fmaf(a3.z, w[it][3].z, v));
                g_V[(((size_t)(bbase + bs) * NI + i) * NO + o) * ND + e] = v;
                float a = ai_s[bs][ii];
                float t = a * v;
                accS[bs] += t;
                accQ[bs] = fmaf(t, v, accQ[bs]);
            }
        }

#pragma unroll
        for (int bs = 0; bs < 8; bs++) { redS[i16][bs][e] = accS[bs]; redQ[i16][bs][e] = accQ[bs]; }
        __syncthreads();
        if (tid < 128) {
            int bs = tid >> 4, ee = tid & 15;
            float S = 0.f, Q = 0.f;
#pragma unroll
            for (int k = 0; k < 16; k++) { S += redS[k][bs][ee]; Q += redQ[k][bs][ee]; }
            int idx = ((bbase + bs) * NO + o) * ND + ee;
            atomicAdd(&g_S1S[idx], S);
            atomicAdd(&g_S1Q[idx], Q);
        }
    }
}

/* ---------------- K1b: per-(b,o) stats from stage-1 sums ---------------- */
__global__ void k1b_stats(const float* __restrict__ beta_a,
                          const float* __restrict__ beta_u)
{
    int idx = blockIdx.x * 256 + threadIdx.x;   /* < 65536 = NB*NO*ND */
    int bo = idx >> 4, e = idx & 15;
    int o = bo & 63, b = bo >> 6;
    float S = g_S1S[idx] * (1.0f / NO);         /* rr = 1/O uniform */
    float Q = g_S1Q[idx] * (1.0f / NO);
    float rs  = g_asum[b] * (1.0f / NO);        /* rr_sum */
    float inv = 1.0f / (rs + EPS);
    float m   = S * inv;
    float var = (Q - 2.0f * m * S + m * m * rs) * inv + 1e-4f;
    float lv  = __logf(var);
    float lsum = lv;
#pragma unroll
    for (int off = 8; off; off >>= 1) lsum += __shfl_xor_sync(0xffffffffu, lsum, off);
    float cost = rs * (16.0f * beta_u[o] + lsum);
    float aj   = 1.0f / (1.0f + __expf(-INVT1 * (beta_a[o] - cost)));
    float p1   = sqrtf(2.0f * 3.14159265358979323846f * __expf(lsum) + EPS);
    g_mean0[idx] = m;
    g_inv2[idx]  = 1.0f / (2.0f * var + EPS);
    if (e == 0) g_c[bo] = aj / (p1 + EPS);
    /* zero k2 accumulators (k1b runs before k2 in-stream) */
    g_S[bo * 33 + e] = 0.f;
    g_S[bo * 33 + 16 + e] = 0.f;
    if (e == 0) g_S[bo * 33 + 32] = 0.f;
}

/* ---------------- K2: fused e-step + m-step-2 accumulation ----------------
 * grid (b, 8 i-chunks of 144); threads 256 = (isub 0..3) x (o 0..63).
 */
__global__ __launch_bounds__(256, 2) void k2_route(void)
{
    int b = blockIdx.x, istart = blockIdx.y * 144;
    int tid = threadIdx.x, o = tid & 63, isub = tid >> 6;
    int bo = b * NO + o;

    float m[16], iv[16];
#pragma unroll
    for (int e = 0; e < 16; e++) { m[e] = g_mean0[bo * ND + e]; iv[e] = g_inv2[bo * ND + e]; }
    float cc = g_c[bo];

    float accw = 0.f, accv[16], accq[16];
#pragma unroll
    for (int e = 0; e < 16; e++) { accv[e] = 0.f; accq[e] = 0.f; }

    __shared__ float wsum[8];
    const float4* V4 = (const float4*)g_V;

    int i0 = istart + isub;
    const float4* p = V4 + ((size_t)(b * NI + i0) * NO + o) * 4;
    float4 r0 = p[0], r1 = p[1], r2 = p[2], r3 = p[3];

    for (int j = 0; j < 36; j++) {
        float4 c0 = r0, c1 = r1, c2 = r2, c3 = r3;
        if (j < 35) {
            const float4* q = V4 + ((size_t)(b * NI + i0 + 4 * (j + 1)) * NO + o) * 4;
            r0 = q[0]; r1 = q[1]; r2 = q[2]; r3 = q[3];
        }
        int i = i0 + 4 * j;
        float V[16];
        V[0]=c0.x; V[1]=c0.y; V[2]=c0.z; V[3]=c0.w;
        V[4]=c1.x; V[5]=c1.y; V[6]=c1.z; V[7]=c1.w;
        V[8]=c2.x; V[9]=c2.y; V[10]=c2.z; V[11]=c2.w;
        V[12]=c3.x; V[13]=c3.y; V[14]=c3.z; V[15]=c3.w;

        float la = 0.f;
#pragma unroll
        for (int e = 0; e < 16; e++) { float d = V[e] - m[e]; la = fmaf(d * d, iv[e], la); }
        float ap = cc * __expf(-la);

        float s = ap;
#pragma unroll
        for (int off = 16; off; off >>= 1) s += __shfl_xor_sync(0xffffffffu, s, off);
        if ((tid & 31) == 0) wsum[tid >> 5] = s;
        __syncthreads();
        float denom = wsum[isub * 2] + wsum[isub * 2 + 1];
        __syncthreads();

        float ai = __ldg(&g_ai[b * NI + i]);
        float wt = ap * ai / (denom + EPS);
        accw += wt;
#pragma unroll
        for (int e = 0; e < 16; e++) {
            accv[e] = fmaf(wt, V[e], accv[e]);
            accq[e] = fmaf(wt * V[e], V[e], accq[e]);
        }
    }

    float* dst = g_S + bo * 33;
#pragma unroll
    for (int e = 0; e < 16; e++) {
        atomicAdd(dst + e, accv[e]);
        atomicAdd(dst + 16 + e, accq[e]);
    }
    atomicAdd(dst + 32, accw);
}

/* ---------------- K3: finalize m-step-2 + output ---------------- */
__global__ void k3_final(const float* __restrict__ beta_a,
                         const float* __restrict__ beta_u,
                         float* __restrict__ out)
{
    int bo = blockIdx.x * 256 + threadIdx.x;
    if (bo >= NB * NO) return;
    int o = bo & 63;
    const float* s = g_S + bo * 33;
    float rs  = s[32];
    float inv = 1.0f / (rs + EPS);
    float bu  = beta_u[o];
    float mm[16];
    float cost = 0.f, norm2 = 0.f;
#pragma unroll
    for (int e = 0; e < 16; e++) {
        float sv = s[e], sq = s[16 + e];
        float me = sv * inv;
        float var = (sq - 2.0f * me * sv + me * me * rs) * inv + 1e-4f;
        cost += bu + __logf(var);
        mm[e] = me;
        float t = me + EPS;
        norm2 = fmaf(t, t, norm2);
    }
    cost *= rs;
    float aj = 1.0f / (1.0f + __expf(-INVT2 * (beta_a[o] - cost)));
    float scale = aj / (sqrtf(norm2) + EPS);
#pragma unroll
    for (int e = 0; e < 16; e++) out[bo * ND + e] = mm[e] * scale;
}

/* ---------------- launch ---------------- */
extern "C" void kernel_launch(void* const* d_in, const int* in_sizes, int n_in,
                              void* d_out, int out_size)
{
    const float* u      = (const float*)d_in[0];
    const float* W      = (const float*)d_in[1];
    const float* beta_a = (const float*)d_in[2];
    const float* beta_u = (const float*)d_in[3];
    const float* bias   = (const float*)d_in[4];
    float* out = (float*)d_out;

    k0_ai<<<NB, 256>>>(u);
    k1_votes<<<dim3(NO, 18), 256>>>((const float4*)u, (const float4*)W, bias);
    k1b_stats<<<256, 256>>>(beta_a, beta_u);
    k2_route<<<dim3(NB, 8), 256>>>();
    k3_final<<<16, 256>>>(beta_a, beta_u, out);
}

// round 5
// speedup vs baseline: 1.5418x; 1.3214x over previous
#include <cuda_runtime.h>
#include <cuda_fp16.h>
#include <math.h>

#define EPS 1e-8f
#define NB 64
#define NO 64
#define NI 1152
#define ND 16
#define INVT1 5.0e-4f            /* 0.01*(1-0.95)   */
#define INVT2 9.75e-4f           /* 0.01*(1-0.9025) */

typedef unsigned long long ull;

/* packed f32x2 helpers (pattern from ptx_helpers.cuh) */
#define PACK2(dst, lo, hi) \
    asm("mov.b64 %0, {%1, %2};" : "=l"(dst) : "r"(__float_as_uint(lo)), "r"(__float_as_uint(hi)))
#define FMA2(acc, a, b) \
    asm("fma.rn.f32x2 %0, %1, %2, %0;" : "+l"(acc) : "l"(a), "l"(b))
#define ADD2(d, a, b) \
    asm("add.rn.f32x2 %0, %1, %2;" : "=l"(d) : "l"(a), "l"(b))
#define UNPK2(lo, hi, v) do { unsigned _ul, _uh; \
    asm("mov.b64 {%0, %1}, %2;" : "=r"(_ul), "=r"(_uh) : "l"(v)); \
    lo = __uint_as_float(_ul); hi = __uint_as_float(_uh); } while (0)
/* dup-pack u_d into both halves, then packed fma — one step of the dot product */
#define STEP(acc, av, wd) do { ull _t; \
    asm("mov.b64 %0, {%1, %1};" : "=l"(_t) : "r"(__float_as_uint(av))); \
    FMA2(acc, _t, wd); } while (0)

/* ---------------- scratch (device globals: allocation-free) ---------------- */
__device__ __half g_Vh[(size_t)NB * NI * NO * ND];  /* [b][i][o][e] fp16, 151 MB */
__device__ float g_ai[NB * NI];
__device__ float g_asum[NB];
__device__ float g_S1S[NB * NO * ND];               /* stage-1: sum a_i*V   */
__device__ float g_S1Q[NB * NO * ND];               /* stage-1: sum a_i*V^2 */
__device__ float g_mean0[NB * NO * ND];
__device__ float g_inv2[NB * NO * ND];
__device__ float g_c[NB * NO];                      /* a_j0/(p1+EPS) */
__device__ float g_S[NB * NO * 33];                 /* [0:16) wV, [16:32) wV^2, [32] w */

/* ---------------- K0: a_i = ||u+eps||, asum[b]; zero stage-1 accumulators -- */
__global__ void k0_ai(const float* __restrict__ u) {
    int b = blockIdx.x, tid = threadIdx.x;
    for (int k = tid; k < 1024; k += 256) {
        g_S1S[b * 1024 + k] = 0.f;
        g_S1Q[b * 1024 + k] = 0.f;
    }
    float part = 0.f;
    for (int i = tid; i < NI; i += 256) {
        const float* ur = u + (b * NI + i) * ND;
        float s = 0.f;
#pragma unroll
        for (int d = 0; d < ND; d++) { float x = ur[d] + EPS; s += x * x; }
        float a = sqrtf(s);
        g_ai[b * NI + i] = a;
        part += a;
    }
    __shared__ float sm[256];
    sm[tid] = part; __syncthreads();
    for (int s = 128; s > 0; s >>= 1) { if (tid < s) sm[tid] += sm[tid + s]; __syncthreads(); }
    if (tid == 0) g_asum[b] = sm[0];
}

/* ---------------- K1: pure votes GEMM, packed f32x2, fp16 stores ----------
 * grid (o=64, ichunk=36 of 32 i). threads 256 = (i_idx=32) x (e-pair p=8).
 * W read once from DRAM into 32 packed regs; loops all 64 b in groups of 8.
 * No reductions, no atomics.
 */
__global__ __launch_bounds__(256) void k1_votes(
    const float4* __restrict__ u4, const float4* __restrict__ W4,
    const float* __restrict__ bias)
{
    int o = blockIdx.x, i0 = blockIdx.y * 32;
    int tid = threadIdx.x, p = tid & 7, i_idx = tid >> 3;

    __shared__ float4 us[8][32][4];   /* 16 KB: u for current b-group */

    /* pack W[o][i0+i_idx][2p..2p+1][d] into 16 f32x2 regs */
    ull w2[16];
    {
        size_t base = ((size_t)o * NI + i0 + i_idx) * ND;
        const float4* r0 = W4 + (base + 2 * p) * 4;
        const float4* r1 = W4 + (base + 2 * p + 1) * 4;
        float4 e0[4], e1[4];
#pragma unroll
        for (int k = 0; k < 4; k++) { e0[k] = r0[k]; e1[k] = r1[k]; }
#pragma unroll
        for (int k = 0; k < 4; k++) {
            PACK2(w2[4 * k + 0], e0[k].x, e1[k].x);
            PACK2(w2[4 * k + 1], e0[k].y, e1[k].y);
            PACK2(w2[4 * k + 2], e0[k].z, e1[k].z);
            PACK2(w2[4 * k + 3], e0[k].w, e1[k].w);
        }
    }
    ull bias2;
    PACK2(bias2, bias[o * ND + 2 * p] + EPS, bias[o * ND + 2 * p + 1] + EPS);

    __half2* Vh2 = (__half2*)g_Vh;

    for (int g = 0; g < 8; g++) {
        __syncthreads();
        for (int n = tid; n < 1024; n += 256) {
            int bs = n >> 7, rem = n & 127, ii = rem >> 2, d4 = rem & 3;
            us[bs][ii][d4] = u4[((size_t)(g * 8 + bs) * NI + i0 + ii) * 4 + d4];
        }
        __syncthreads();

#pragma unroll
        for (int bs = 0; bs < 8; bs++) {
            float4 a0 = us[bs][i_idx][0], a1 = us[bs][i_idx][1];
            float4 a2 = us[bs][i_idx][2], a3 = us[bs][i_idx][3];
            ull va = bias2, vb = 0ull;   /* (0.0f,0.0f) */
            STEP(va, a0.x, w2[0]);  STEP(vb, a0.y, w2[1]);
            STEP(va, a0.z, w2[2]);  STEP(vb, a0.w, w2[3]);
            STEP(va, a1.x, w2[4]);  STEP(vb, a1.y, w2[5]);
            STEP(va, a1.z, w2[6]);  STEP(vb, a1.w, w2[7]);
            STEP(va, a2.x, w2[8]);  STEP(vb, a2.y, w2[9]);
            STEP(va, a2.z, w2[10]); STEP(vb, a2.w, w2[11]);
            STEP(va, a3.x, w2[12]); STEP(vb, a3.y, w2[13]);
            STEP(va, a3.z, w2[14]); STEP(vb, a3.w, w2[15]);
            ull v2; ADD2(v2, va, vb);
            float lo, hi; UNPK2(lo, hi, v2);
            size_t idx = (((size_t)(g * 8 + bs) * NI + i0 + i_idx) * NO + o) * 8 + p;
            Vh2[idx] = __floats2half2_rn(lo, hi);
        }
    }
}

/* ---------------- K1s: stage-1 sums (uniform rr) from fp16 V --------------
 * grid (b=64, 18 chunks of 64 i); threads 256 = (o=64) x (e-quad q=4).
 */
__global__ __launch_bounds__(256) void k1s_sums(void)
{
    int b = blockIdx.x, i0 = blockIdx.y * 64;
    int tid = threadIdx.x, q = tid & 3, o = tid >> 2;
    float S[4] = {0.f, 0.f, 0.f, 0.f}, Q[4] = {0.f, 0.f, 0.f, 0.f};
    for (int ii = 0; ii < 64; ii++) {
        int i = i0 + ii;
        float ai = __ldg(&g_ai[b * NI + i]);
        const uint2* pv = (const uint2*)(g_Vh + (((size_t)b * NI + i) * NO + o) * ND + q * 4);
        uint2 raw = *pv;
        float2 f0 = __half22float2(*(const __half2*)&raw.x);
        float2 f1 = __half22float2(*(const __half2*)&raw.y);
        float t0 = ai * f0.x, t1 = ai * f0.y, t2 = ai * f1.x, t3 = ai * f1.y;
        S[0] += t0; S[1] += t1; S[2] += t2; S[3] += t3;
        Q[0] = fmaf(t0, f0.x, Q[0]); Q[1] = fmaf(t1, f0.y, Q[1]);
        Q[2] = fmaf(t2, f1.x, Q[2]); Q[3] = fmaf(t3, f1.y, Q[3]);
    }
    int base = (b * NO + o) * ND + q * 4;
#pragma unroll
    for (int k = 0; k < 4; k++) {
        atomicAdd(&g_S1S[base + k], S[k]);
        atomicAdd(&g_S1Q[base + k], Q[k]);
    }
}

/* ---------------- K1b: per-(b,o) stats from stage-1 sums ---------------- */
__global__ void k1b_stats(const float* __restrict__ beta_a,
                          const float* __restrict__ beta_u)
{
    int idx = blockIdx.x * 256 + threadIdx.x;   /* < 65536 = NB*NO*ND */
    int bo = idx >> 4, e = idx & 15;
    int o = bo & 63, b = bo >> 6;
    float S = g_S1S[idx] * (1.0f / NO);
    float Q = g_S1Q[idx] * (1.0f / NO);
    float rs  = g_asum[b] * (1.0f / NO);
    float inv = 1.0f / (rs + EPS);
    float m   = S * inv;
    float var = (Q - 2.0f * m * S + m * m * rs) * inv + 1e-4f;
    float lv  = __logf(var);
    float lsum = lv;
#pragma unroll
    for (int off = 8; off; off >>= 1) lsum += __shfl_xor_sync(0xffffffffu, lsum, off);
    float cost = rs * (16.0f * beta_u[o] + lsum);
    float aj   = 1.0f / (1.0f + __expf(-INVT1 * (beta_a[o] - cost)));
    float p1   = sqrtf(2.0f * 3.14159265358979323846f * __expf(lsum) + EPS);
    g_mean0[idx] = m;
    g_inv2[idx]  = 1.0f / (2.0f * var + EPS);
    if (e == 0) g_c[bo] = aj / (p1 + EPS);
    g_S[bo * 33 + e] = 0.f;
    g_S[bo * 33 + 16 + e] = 0.f;
    if (e == 0) g_S[bo * 33 + 32] = 0.f;
}

/* ---------------- K2: fused e-step + m-step-2, 2 barriers total -----------
 * grid (b=64, 32 tiles of 36 i); threads 256 = (isub=4) x (o=64).
 * Phase A: ap for all 9 i/thread (regs + smem). Barrier.
 * Phase B: parallel per-i denominators -> s_i = ai/denom. Barrier.
 * Phase C: reload V (L2-hot), accumulate. Phase D: smem pre-reduce + atomics.
 */
__global__ __launch_bounds__(256) void k2_route(void)
{
    __shared__ float smem_buf[8448];  /* 33 KB: aps[36*64]+sden[36] / accsm[33*4*64] */
    float* aps  = smem_buf;           /* [i_loc][o] */
    float* sden = smem_buf + 2304;    /* [i_loc]    */

    int b = blockIdx.x, i0 = blockIdx.y * 36;
    int tid = threadIdx.x, o = tid & 63, isub = tid >> 6;
    int bo = b * NO + o;

    float m[16], iv[16];
    {
        const float4* pm = (const float4*)(g_mean0 + bo * ND);
        const float4* pi = (const float4*)(g_inv2  + bo * ND);
#pragma unroll
        for (int k = 0; k < 4; k++) {
            float4 a = pm[k], c = pi[k];
            m[4*k]=a.x; m[4*k+1]=a.y; m[4*k+2]=a.z; m[4*k+3]=a.w;
            iv[4*k]=c.x; iv[4*k+1]=c.y; iv[4*k+2]=c.z; iv[4*k+3]=c.w;
        }
    }
    float cc = g_c[bo];
    const uint4* V4 = (const uint4*)g_Vh;

    float ap_r[9];
#pragma unroll
    for (int j = 0; j < 9; j++) {
        int il = j * 4 + isub;
        size_t base = (((size_t)b * NI + i0 + il) * NO + o) * 2;
        uint4 x0 = V4[base], x1 = V4[base + 1];
        float v[16];
        {
            float2 f;
            f = __half22float2(*(const __half2*)&x0.x); v[0]=f.x; v[1]=f.y;
            f = __half22float2(*(const __half2*)&x0.y); v[2]=f.x; v[3]=f.y;
            f = __half22float2(*(const __half2*)&x0.z); v[4]=f.x; v[5]=f.y;
            f = __half22float2(*(const __half2*)&x0.w); v[6]=f.x; v[7]=f.y;
            f = __half22float2(*(const __half2*)&x1.x); v[8]=f.x; v[9]=f.y;
            f = __half22float2(*(const __half2*)&x1.y); v[10]=f.x; v[11]=f.y;
            f = __half22float2(*(const __half2*)&x1.z); v[12]=f.x; v[13]=f.y;
            f = __half22float2(*(const __half2*)&x1.w); v[14]=f.x; v[15]=f.y;
        }
        float la = 0.f;
#pragma unroll
        for (int e = 0; e < 16; e++) { float d = v[e] - m[e]; la = fmaf(d * d, iv[e], la); }
        float ap = cc * __expf(-la);
        ap_r[j] = ap;
        aps[il * 64 + o] = ap;
    }
    __syncthreads();

    if (tid < 160) {                    /* 5 full warps; il 0..39, guard at 36 */
        int q = tid & 3, il = tid >> 2;
        float s = 0.f;
        if (il < 36) {
            const float* row = aps + il * 64 + q * 16;
#pragma unroll
            for (int k = 0; k < 16; k++) s += row[k];
        }
        s += __shfl_xor_sync(0xffffffffu, s, 1);
        s += __shfl_xor_sync(0xffffffffu, s, 2);
        if (q == 0 && il < 36)
            sden[il] = __ldg(&g_ai[b * NI + i0 + il]) / (s + EPS);
    }
    __syncthreads();

    float accw = 0.f, accv[16], accq[16];
#pragma unroll
    for (int e = 0; e < 16; e++) { accv[e] = 0.f; accq[e] = 0.f; }

#pragma unroll
    for (int j = 0; j < 9; j++) {
        int il = j * 4 + isub;
        size_t base = (((size_t)b * NI + i0 + il) * NO + o) * 2;
        uint4 x0 = V4[base], x1 = V4[base + 1];
        float v[16];
        {
            float2 f;
            f = __half22float2(*(const __half2*)&x0.x); v[0]=f.x; v[1]=f.y;
            f = __half22float2(*(const __half2*)&x0.y); v[2]=f.x; v[3]=f.y;
            f = __half22float2(*(const __half2*)&x0.z); v[4]=f.x; v[5]=f.y;
            f = __half22float2(*(const __half2*)&x0.w); v[6]=f.x; v[7]=f.y;
            f = __half22float2(*(const __half2*)&x1.x); v[8]=f.x; v[9]=f.y;
            f = __half22float2(*(const __half2*)&x1.y); v[10]=f.x; v[11]=f.y;
            f = __half22float2(*(const __half2*)&x1.z); v[12]=f.x; v[13]=f.y;
            f = __half22float2(*(const __half2*)&x1.w); v[14]=f.x; v[15]=f.y;
        }
        float wt = ap_r[j] * sden[il];
        accw += wt;
#pragma unroll
        for (int e = 0; e < 16; e++) {
            accv[e] = fmaf(wt, v[e], accv[e]);
            accq[e] = fmaf(wt * v[e], v[e], accq[e]);
        }
    }
    __syncthreads();   /* aps/sden dead; overlay accsm */

    float* accsm = smem_buf;           /* [k=33][isub=4][o=64] */
#pragma unroll
    for (int e = 0; e < 16; e++) {
        accsm[e * 256 + isub * 64 + o]        = accv[e];
        accsm[(16 + e) * 256 + isub * 64 + o] = accq[e];
    }
    accsm[32 * 256 + isub * 64 + o] = accw;
    __syncthreads();

    {
        int o2 = tid & 63, ks = tid >> 6;
        for (int k = ks; k < 33; k += 4) {
            const float* r = accsm + k * 256 + o2;
            float s = r[0] + r[64] + r[128] + r[192];
            atomicAdd(&g_S[(b * NO + o2) * 33 + k], s);
        }
    }
}

/* ---------------- K3: finalize m-step-2 + output ---------------- */
__global__ void k3_final(const float* __restrict__ beta_a,
                         const float* __restrict__ beta_u,
                         float* __restrict__ out)
{
    int bo = blockIdx.x * 256 + threadIdx.x;
    if (bo >= NB * NO) return;
    int o = bo & 63;
    const float* s = g_S + bo * 33;
    float rs  = s[32];
    float inv = 1.0f / (rs + EPS);
    float bu  = beta_u[o];
    float mm[16];
    float cost = 0.f, norm2 = 0.f;
#pragma unroll
    for (int e = 0; e < 16; e++) {
        float sv = s[e], sq = s[16 + e];
        float me = sv * inv;
        float var = (sq - 2.0f * me * sv + me * me * rs) * inv + 1e-4f;
        cost += bu + __logf(var);
        mm[e] = me;
        float t = me + EPS;
        norm2 = fmaf(t, t, norm2);
    }
    cost *= rs;
    float aj = 1.0f / (1.0f + __expf(-INVT2 * (beta_a[o] - cost)));
    float scale = aj / (sqrtf(norm2) + EPS);
#pragma unroll
    for (int e = 0; e < 16; e++) out[bo * ND + e] = mm[e] * scale;
}

/* ---------------- launch ---------------- */
extern "C" void kernel_launch(void* const* d_in, const int* in_sizes, int n_in,
                              void* d_out, int out_size)
{
    const float* u      = (const float*)d_in[0];
    const float* W      = (const float*)d_in[1];
    const float* beta_a = (const float*)d_in[2];
    const float* beta_u = (const float*)d_in[3];
    const float* bias   = (const float*)d_in[4];
    float* out = (float*)d_out;

    k0_ai<<<NB, 256>>>(u);
    k1_votes<<<dim3(NO, 36), 256>>>((const float4*)u, (const float4*)W, bias);
    k1s_sums<<<dim3(NB, 18), 256>>>();
    k1b_stats<<<256, 256>>>(beta_a, beta_u);
    k2_route<<<dim3(NB, 32), 256>>>();
    k3_final<<<16, 256>>>(beta_a, beta_u, out);
}